// round 2
// baseline (speedup 1.0000x reference)
#include <cuda_runtime.h>
#include <math.h>

// Problem constants (fixed by setup_inputs)
#define C_IN   64
#define C_OUT  128
#define NPAIR  2048            // B*T = 16*128
#define WSTRIDE 129            // padded shared stride for weight (bank-conflict-free)

#define THREADS 256            // 2 pairs x 128 output channels
#define PAIRS_PER_BLOCK 2

__global__ __launch_bounds__(THREADS, 4)
void qpu_kernel(const float* __restrict__ x,      // (NPAIR, 4*C_IN) [r|i|j|k]
                const float* __restrict__ weight, // (C_OUT, C_IN)
                const float* __restrict__ bias,   // (C_OUT)
                float* __restrict__ out)          // (NPAIR, 4*C_OUT)
{
    __shared__ float  w_s[C_IN * WSTRIDE];        // transposed: w_s[c*129 + o]
    __shared__ float4 pc[PAIRS_PER_BLOCK][C_IN];  // {theta0, i*rn, j*rn, k*rn}

    const int tid = threadIdx.x;
    const int p0  = blockIdx.x * PAIRS_PER_BLOCK;

    // ---- stage weight into shared, transposed ----
    #pragma unroll
    for (int idx = tid; idx < C_OUT * C_IN; idx += THREADS) {
        int o = idx >> 6;       // /C_IN
        int c = idx & 63;       // %C_IN
        w_s[c * WSTRIDE + o] = weight[idx];
    }

    // ---- per-(pair,c) preprocessing: theta0 = acos(clip(r)), prescaled i,j,k ----
    if (tid < PAIRS_PER_BLOCK * C_IN) {
        int pp = tid >> 6;
        int c  = tid & 63;
        const float* xr = x + (size_t)(p0 + pp) * (4 * C_IN);
        float r = xr[c];
        float i = xr[C_IN + c];
        float j = xr[2 * C_IN + c];
        float k = xr[3 * C_IN + c];
        float rn = rsqrtf(fmaf(i, i, fmaf(j, j, fmaf(k, k, 1e-12f))));
        const float CLAMP = 1.0f - 1e-6f;
        float rc = fminf(fmaxf(r, -CLAMP), CLAMP);
        float t0 = acosf(rc);
        pc[pp][c] = make_float4(t0, i * rn, j * rn, k * rn);
    }
    __syncthreads();

    // ---- main loop: one thread = one (pair, o) ----
    const int pp = tid >> 7;        // which pair within block
    const int o  = tid & 127;       // output channel
    const float b = bias[o];

    // minimax sin/cos on |x| <= ~0.8 (theta bounded by |w|*pi + |b| < pi/4 here)
    const float S1 = -1.6666654611e-1f, S2 = 8.3321608736e-3f, S3 = -1.9515295891e-4f;
    const float Cc1 = 4.16666418e-2f,   Cc2 = -1.388731625e-3f;

    float ar = 1.0f, ai = 0.0f, aj = 0.0f, ak = 0.0f;

    #pragma unroll 4
    for (int c = 0; c < C_IN; ++c) {
        float4 p = pc[pp][c];
        float  w = w_s[c * WSTRIDE + o];

        float th = fmaf(w, p.x, b);
        float x2 = th * th;

        // sin(th)
        float ps = fmaf(x2, S3, S2);
        ps = fmaf(x2, ps, S1);
        float s = fmaf(ps * x2, th, th);
        // cos(th)
        float pq = fmaf(x2, Cc2, Cc1);
        pq = fmaf(x2, pq, -0.5f);
        float qr = fmaf(x2, pq, 1.0f);

        float qi = p.y * s;
        float qj = p.z * s;
        float qk = p.w * s;

        // acc = acc (x) q  (Hamilton)
        float nr = ar * qr; nr = fmaf(-ai, qi, nr); nr = fmaf(-aj, qj, nr); nr = fmaf(-ak, qk, nr);
        float ni = ar * qi; ni = fmaf( ai, qr, ni); ni = fmaf( aj, qk, ni); ni = fmaf(-ak, qj, ni);
        float nj = ar * qj; nj = fmaf(-ai, qk, nj); nj = fmaf( aj, qr, nj); nj = fmaf( ak, qi, nj);
        float nk = ar * qk; nk = fmaf( ai, qj, nk); nk = fmaf(-aj, qi, nk); nk = fmaf( ak, qr, nk);
        ar = nr; ai = ni; aj = nj; ak = nk;
    }

    // normalize + write (coalesced over o)
    float n2 = fmaf(ar, ar, fmaf(ai, ai, fmaf(aj, aj, fmaf(ak, ak, 1e-12f))));
    float rn = rsqrtf(n2);
    float* op = out + (size_t)(p0 + pp) * (4 * C_OUT);
    op[o]             = ar * rn;
    op[C_OUT + o]     = ai * rn;
    op[2 * C_OUT + o] = aj * rn;
    op[3 * C_OUT + o] = ak * rn;
}

extern "C" void kernel_launch(void* const* d_in, const int* in_sizes, int n_in,
                              void* d_out, int out_size) {
    const float* x      = (const float*)d_in[0];
    const float* weight = (const float*)d_in[1];
    const float* bias   = (const float*)d_in[2];
    float* out = (float*)d_out;
    (void)in_sizes; (void)n_in; (void)out_size;

    dim3 grid(NPAIR / PAIRS_PER_BLOCK);   // 1024 blocks
    qpu_kernel<<<grid, THREADS>>>(x, weight, bias, out);
}

// round 3
// speedup vs baseline: 1.0089x; 1.0089x over previous
#include <cuda_runtime.h>
#include <math.h>

// Problem constants (fixed by setup_inputs)
#define C_IN   64
#define C_OUT  128
#define NPAIR  2048            // B*T = 16*128
#define WSTRIDE 129            // padded: conflict-free transposed STORE phase
#define THREADS 256
#define PAIRS_PER_BLOCK 4      // 2 pair-pairs, each packed into f32x2 lanes

typedef unsigned long long u64;

__device__ __forceinline__ u64 pack2(float a, float b) {
    u64 r; asm("mov.b64 %0, {%1, %2};" : "=l"(r) : "f"(a), "f"(b)); return r;
}
__device__ __forceinline__ void unpack2(u64 v, float& a, float& b) {
    asm("mov.b64 {%0, %1}, %2;" : "=f"(a), "=f"(b) : "l"(v));
}
__device__ __forceinline__ u64 fma2(u64 a, u64 b, u64 c) {
    u64 r; asm("fma.rn.f32x2 %0, %1, %2, %3;" : "=l"(r) : "l"(a), "l"(b), "l"(c)); return r;
}
__device__ __forceinline__ u64 mul2(u64 a, u64 b) {
    u64 r; asm("mul.rn.f32x2 %0, %1, %2;" : "=l"(r) : "l"(a), "l"(b)); return r;
}
// negate both packed floats via sign-bit xor (alu pipe, keeps fma pipe free)
__device__ __forceinline__ u64 neg2(u64 a) { return a ^ 0x8000000080000000ULL; }

__global__ __launch_bounds__(THREADS, 3)
void qpu_kernel(const float* __restrict__ x,      // (NPAIR, 4*C_IN) [r|i|j|k]
                const float* __restrict__ weight, // (C_OUT, C_IN)
                const float* __restrict__ bias,   // (C_OUT)
                float* __restrict__ out)          // (NPAIR, 4*C_OUT)
{
    __shared__ float w_s[C_IN * WSTRIDE];         // transposed: w_s[c*129 + o]
    // packed per-c preprocess: [pair-pair][c] -> {th0(p0,p1), i(p0,p1)}, {j(p0,p1), k(p0,p1)}
    __shared__ ulonglong2 pcs[2][C_IN][2];

    const int tid = threadIdx.x;
    const int p0  = blockIdx.x * PAIRS_PER_BLOCK;

    // ---- stage weight into shared, transposed ----
    #pragma unroll
    for (int idx = tid; idx < C_OUT * C_IN; idx += THREADS) {
        int o = idx >> 6;       // /C_IN
        int c = idx & 63;       // %C_IN
        w_s[c * WSTRIDE + o] = weight[idx];
    }

    // ---- per-(pair,c) preprocessing, written pair-interleaved for packed reads ----
    {
        int pair = tid >> 6;    // 0..3
        int c    = tid & 63;
        const float* xr = x + (size_t)(p0 + pair) * (4 * C_IN);
        float r = xr[c];
        float i = xr[C_IN + c];
        float j = xr[2 * C_IN + c];
        float k = xr[3 * C_IN + c];
        float rn = rsqrtf(fmaf(i, i, fmaf(j, j, fmaf(k, k, 1e-12f))));
        const float CL = 1.0f - 1e-6f;
        float t0 = acosf(fminf(fmaxf(r, -CL), CL));
        float* dst = (float*)&pcs[pair >> 1][c][0];
        int par = pair & 1;
        dst[0 + par] = t0;
        dst[2 + par] = i * rn;
        dst[4 + par] = j * rn;
        dst[6 + par] = k * rn;
    }
    __syncthreads();

    // ---- main loop: one thread = (2 pairs, one o), all math packed f32x2 ----
    const int pp = tid >> 7;        // which pair-pair
    const int o  = tid & 127;       // output channel
    const float b = bias[o];
    const u64 bp  = pack2(b, b);
    const u64 S1p = pack2(-1.6666654611e-1f, -1.6666654611e-1f);
    const u64 S2p = pack2( 8.3321608736e-3f,  8.3321608736e-3f);
    const u64 C1p = pack2( 4.16666418e-2f,    4.16666418e-2f);
    const u64 C2p = pack2(-1.388731625e-3f,  -1.388731625e-3f);
    const u64 NHp = pack2(-0.5f, -0.5f);
    const u64 ONEp= pack2( 1.0f,  1.0f);

    u64 ar, ai, aj, ak;

    // peel c = 0: acc = q (identity product)
    {
        ulonglong2 q0 = pcs[pp][0][0];
        ulonglong2 q1 = pcs[pp][0][1];
        float w = w_s[o];
        u64 wp = pack2(w, w);
        u64 th = fma2(wp, q0.x, bp);
        u64 x2 = mul2(th, th);
        u64 ps = fma2(x2, S2p, S1p);
        u64 s  = fma2(mul2(ps, x2), th, th);
        u64 pq = fma2(x2, C2p, C1p);
        pq = fma2(x2, pq, NHp);
        ar = fma2(x2, pq, ONEp);
        ai = mul2(q0.y, s);
        aj = mul2(q1.x, s);
        ak = mul2(q1.y, s);
    }

    #pragma unroll 16
    for (int c = 1; c < C_IN; ++c) {
        ulonglong2 q0 = pcs[pp][c][0];
        ulonglong2 q1 = pcs[pp][c][1];
        float w = w_s[c * WSTRIDE + o];
        u64 wp = pack2(w, w);

        u64 th = fma2(wp, q0.x, bp);
        u64 x2 = mul2(th, th);
        // sin (deg 5)
        u64 ps = fma2(x2, S2p, S1p);
        u64 s  = fma2(mul2(ps, x2), th, th);
        // cos (deg 6)
        u64 pq = fma2(x2, C2p, C1p);
        pq = fma2(x2, pq, NHp);
        u64 qr = fma2(x2, pq, ONEp);

        u64 qi = mul2(q0.y, s);
        u64 qj = mul2(q1.x, s);
        u64 qk = mul2(q1.y, s);

        u64 nai = neg2(ai), naj = neg2(aj), nak = neg2(ak);

        // acc = acc (x) q  (Hamilton), packed over two pairs
        u64 nr = mul2(ar, qr); nr = fma2(nai, qi, nr); nr = fma2(naj, qj, nr); nr = fma2(nak, qk, nr);
        u64 ni = mul2(ar, qi); ni = fma2(ai,  qr, ni); ni = fma2(aj,  qk, ni); ni = fma2(nak, qj, ni);
        u64 nj = mul2(ar, qj); nj = fma2(nai, qk, nj); nj = fma2(aj,  qr, nj); nj = fma2(ak,  qi, nj);
        u64 nk = mul2(ar, qk); nk = fma2(ai,  qj, nk); nk = fma2(naj, qi, nk); nk = fma2(ak,  qr, nk);
        ar = nr; ai = ni; aj = nj; ak = nk;
    }

    // ---- unpack, normalize both pairs, coalesced writes ----
    float ar0, ar1, ai0, ai1, aj0, aj1, ak0, ak1;
    unpack2(ar, ar0, ar1);
    unpack2(ai, ai0, ai1);
    unpack2(aj, aj0, aj1);
    unpack2(ak, ak0, ak1);

    float n0 = rsqrtf(fmaf(ar0, ar0, fmaf(ai0, ai0, fmaf(aj0, aj0, fmaf(ak0, ak0, 1e-12f)))));
    float n1 = rsqrtf(fmaf(ar1, ar1, fmaf(ai1, ai1, fmaf(aj1, aj1, fmaf(ak1, ak1, 1e-12f)))));

    float* op0 = out + (size_t)(p0 + pp * 2) * (4 * C_OUT);
    float* op1 = op0 + 4 * C_OUT;
    op0[o]             = ar0 * n0;
    op0[C_OUT + o]     = ai0 * n0;
    op0[2 * C_OUT + o] = aj0 * n0;
    op0[3 * C_OUT + o] = ak0 * n0;
    op1[o]             = ar1 * n1;
    op1[C_OUT + o]     = ai1 * n1;
    op1[2 * C_OUT + o] = aj1 * n1;
    op1[3 * C_OUT + o] = ak1 * n1;
}

extern "C" void kernel_launch(void* const* d_in, const int* in_sizes, int n_in,
                              void* d_out, int out_size) {
    const float* x      = (const float*)d_in[0];
    const float* weight = (const float*)d_in[1];
    const float* bias   = (const float*)d_in[2];
    float* out = (float*)d_out;
    (void)in_sizes; (void)n_in; (void)out_size;

    dim3 grid(NPAIR / PAIRS_PER_BLOCK);   // 512 blocks
    qpu_kernel<<<grid, THREADS>>>(x, weight, bias, out);
}

// round 4
// speedup vs baseline: 1.2076x; 1.1969x over previous
#include <cuda_runtime.h>
#include <math.h>

// Problem constants (fixed by setup_inputs)
#define C_IN   64
#define C_OUT  128
#define NPAIR  2048            // B*T = 16*128
#define WSTRIDE 129            // padded shared stride for weight (bank-conflict-free)

#define THREADS 256            // 2 pairs x 128 output channels
#define PAIRS_PER_BLOCK 2

__global__ __launch_bounds__(THREADS, 5)
void qpu_kernel(const float* __restrict__ x,      // (NPAIR, 4*C_IN) [r|i|j|k]
                const float* __restrict__ weight, // (C_OUT, C_IN)
                const float* __restrict__ bias,   // (C_OUT)
                float* __restrict__ out)          // (NPAIR, 4*C_OUT)
{
    __shared__ float  w_s[C_IN * WSTRIDE];        // transposed: w_s[c*129 + o]
    __shared__ float4 pc[PAIRS_PER_BLOCK][C_IN];  // {theta0, i*rn, j*rn, k*rn}

    const int tid = threadIdx.x;
    const int p0  = blockIdx.x * PAIRS_PER_BLOCK;

    // ---- stage weight into shared, transposed ----
    #pragma unroll
    for (int idx = tid; idx < C_OUT * C_IN; idx += THREADS) {
        int o = idx >> 6;       // /C_IN
        int c = idx & 63;       // %C_IN
        w_s[c * WSTRIDE + o] = weight[idx];
    }

    // ---- per-(pair,c) preprocessing: theta0 = acos(clip(r)), prescaled axis ----
    if (tid < PAIRS_PER_BLOCK * C_IN) {
        int pp = tid >> 6;
        int c  = tid & 63;
        const float* xr = x + (size_t)(p0 + pp) * (4 * C_IN);
        float r = xr[c];
        float i = xr[C_IN + c];
        float j = xr[2 * C_IN + c];
        float k = xr[3 * C_IN + c];
        float rn = rsqrtf(fmaf(i, i, fmaf(j, j, fmaf(k, k, 1e-12f))));
        const float CLAMP = 1.0f - 1e-6f;
        float rc = fminf(fmaxf(r, -CLAMP), CLAMP);
        float t0 = acosf(rc);
        pc[pp][c] = make_float4(t0, i * rn, j * rn, k * rn);
    }
    __syncthreads();

    // ---- main loop: one thread = one (pair, o) ----
    const int pp = tid >> 7;        // which pair within block
    const int o  = tid & 127;       // output channel
    const float b = bias[o];

    // Accumulator in tan-normalized form: implicit scale = prod(cos th_c),
    // recovered for free by the final normalization.
    float ar = 1.0f, ai = 0.0f, aj = 0.0f, ak = 0.0f;

    #pragma unroll 8
    for (int c = 0; c < C_IN; ++c) {
        float4 p = pc[pp][c];
        float  w = w_s[c * WSTRIDE + o];

        float th = fmaf(w, p.x, b);             // |th| <= 0.733 < pi/2
        float s  = __sinf(th);                  // MUFU.SIN
        float cc = __cosf(th);                  // MUFU.COS
        float t  = s * __frcp_rn(cc);           // placeholder; replaced below
        // use fast reciprocal (MUFU.RCP) explicitly:
        t = __fdividef(s, cc);                  // s * MUFU.RCP(cc)

        float qi = p.y * t;
        float qj = p.z * t;
        float qk = p.w * t;

        // acc = acc (x) (1, qi, qj, qk)   -- 12 FMA
        float nr = ar; nr = fmaf(-ai, qi, nr); nr = fmaf(-aj, qj, nr); nr = fmaf(-ak, qk, nr);
        float ni = ai; ni = fmaf( ar, qi, ni); ni = fmaf( aj, qk, ni); ni = fmaf(-ak, qj, ni);
        float nj = aj; nj = fmaf( ar, qj, nj); nj = fmaf(-ai, qk, nj); nj = fmaf( ak, qi, nj);
        float nk = ak; nk = fmaf( ar, qk, nk); nk = fmaf( ai, qj, nk); nk = fmaf(-aj, qi, nk);
        ar = nr; ai = ni; aj = nj; ak = nk;
    }

    // normalize + write (coalesced over o)
    float n2 = fmaf(ar, ar, fmaf(ai, ai, fmaf(aj, aj, fmaf(ak, ak, 1e-12f))));
    float rn = rsqrtf(n2);
    float* op = out + (size_t)(p0 + pp) * (4 * C_OUT);
    op[o]             = ar * rn;
    op[C_OUT + o]     = ai * rn;
    op[2 * C_OUT + o] = aj * rn;
    op[3 * C_OUT + o] = ak * rn;
}

extern "C" void kernel_launch(void* const* d_in, const int* in_sizes, int n_in,
                              void* d_out, int out_size) {
    const float* x      = (const float*)d_in[0];
    const float* weight = (const float*)d_in[1];
    const float* bias   = (const float*)d_in[2];
    float* out = (float*)d_out;
    (void)in_sizes; (void)n_in; (void)out_size;

    dim3 grid(NPAIR / PAIRS_PER_BLOCK);   // 1024 blocks
    qpu_kernel<<<grid, THREADS>>>(x, weight, bias, out);
}